// round 11
// baseline (speedup 1.0000x reference)
#include <cuda_runtime.h>
#include <cstdint>

// Problem constants (fixed by the reference)
#define E    1024
#define NBLK 6
#define FF   4096
#define CC   1000
#define BB   4096

// ---------------- device scratch (no allocations allowed) ----------------
// NOTE: __align__(16) is load-bearing — these are accessed through float4*.
__device__ __align__(16) float g_M[NBLK * E * 8]; // precomputed Wo@Wv (E x 8 per block)
__device__ __align__(16) float g_f[E];            // f vector of current block
__device__ __align__(16) float g_h1[E];           // h-after-LN1 of current block
__device__ __align__(16) float g_r[FF];           // r vector for the NEXT dot kernel
__device__ __align__(16) float g_hfin[E];         // final h after LN2 of block 5
__device__ __align__(16) float g_row[CC];         // classifier row
__device__ unsigned g_cnt[8];                     // completion counters (zero-init; reset in-kernel)

__device__ __forceinline__ float dot4(float4 a, float4 b) {
    return fmaf(a.x, b.x, fmaf(a.y, b.y, fmaf(a.z, b.z, a.w * b.w)));
}

// ============ block prologue, executed by ONE 256-thread CTA ==============
// For nb in [1..NBLK]: h_in = LN2_{nb-1}(g_h1 + g_f). For nb==0: h_in = h0.
// For nb==NBLK: store h_in to g_hfin and return.
// Else: attn = M_nb @ cos(h_in[:8]+phi_q_nb); h1 = LN1_nb(h_in+attn) -> g_h1;
//       r = relu(W1_nb @ (cos(h1[:4])*cos(phi_f_nb))) -> g_r.
__device__ void block_prologue(int nb,
    const float* __restrict__ W1,
    const float* __restrict__ phi_q, const float* __restrict__ phi_f,
    const float* __restrict__ ln1_g, const float* __restrict__ ln1_b,
    const float* __restrict__ ln2_g, const float* __restrict__ ln2_b)
{
    __shared__ __align__(16) float hs[E];
    __shared__ float red1[8], red2[8], stats[2], ms[8];
    const int tid = threadIdx.x, lane = tid & 31, w = tid >> 5;

    // ---- h_in: 4 values per thread (float4 index = tid) ----
    float4 hin;
    if (nb == 0) {
        hin = make_float4(1.f, 2.f, 1.f, 2.f);     // h0 = 1 + pe0
    } else {
        float4 a = ((const float4*)g_h1)[tid];
        float4 b = ((const float4*)g_f)[tid];
        hin = make_float4(a.x + b.x, a.y + b.y, a.z + b.z, a.w + b.w);
        float s1 = hin.x + hin.y + hin.z + hin.w;
        float s2 = hin.x*hin.x + hin.y*hin.y + hin.z*hin.z + hin.w*hin.w;
#pragma unroll
        for (int o = 16; o; o >>= 1) {
            s1 += __shfl_xor_sync(0xffffffffu, s1, o);
            s2 += __shfl_xor_sync(0xffffffffu, s2, o);
        }
        if (lane == 0) { red1[w] = s1; red2[w] = s2; }
        __syncthreads();
        if (tid == 0) {
            float t1 = 0.f, t2 = 0.f;
#pragma unroll
            for (int i = 0; i < 8; i++) { t1 += red1[i]; t2 += red2[i]; }
            float mean = t1 * (1.0f / E);
            float var  = t2 * (1.0f / E) - mean * mean;
            stats[0] = mean;
            stats[1] = rsqrtf(fmaxf(var, 0.f) + 1e-5f);
        }
        __syncthreads();
        float mean = stats[0], rstd = stats[1];
        float4 g4 = ((const float4*)(ln2_g + (size_t)(nb - 1) * E))[tid];
        float4 b4 = ((const float4*)(ln2_b + (size_t)(nb - 1) * E))[tid];
        hin.x = (hin.x - mean) * rstd * g4.x + b4.x;
        hin.y = (hin.y - mean) * rstd * g4.y + b4.y;
        hin.z = (hin.z - mean) * rstd * g4.z + b4.z;
        hin.w = (hin.w - mean) * rstd * g4.w + b4.w;
    }
    if (nb == NBLK) { ((float4*)g_hfin)[tid] = hin; return; }

    ((float4*)hs)[tid] = hin;
    __syncthreads();
    if (tid < 8) ms[tid] = cosf(hs[tid] + phi_q[nb * 8 + tid]);
    __syncthreads();
    float m0 = ms[0], m1 = ms[1], m2 = ms[2], m3 = ms[3];
    float m4 = ms[4], m5 = ms[5], m6 = ms[6], m7 = ms[7];

    // ---- attn for this thread's 4 rows, then h1 = LN1(h_in + attn) ----
    float at[4];
#pragma unroll
    for (int j = 0; j < 4; j++) {
        const float4* mr = (const float4*)(g_M + ((size_t)nb * E + 4 * tid + j) * 8);
        float4 a = mr[0], c = mr[1];
        at[j] = a.x*m0 + a.y*m1 + a.z*m2 + a.w*m3
              + c.x*m4 + c.y*m5 + c.z*m6 + c.w*m7;
    }
    float4 v = make_float4(hin.x + at[0], hin.y + at[1], hin.z + at[2], hin.w + at[3]);
    {
        float s1 = v.x + v.y + v.z + v.w;
        float s2 = v.x*v.x + v.y*v.y + v.z*v.z + v.w*v.w;
#pragma unroll
        for (int o = 16; o; o >>= 1) {
            s1 += __shfl_xor_sync(0xffffffffu, s1, o);
            s2 += __shfl_xor_sync(0xffffffffu, s2, o);
        }
        if (lane == 0) { red1[w] = s1; red2[w] = s2; }
        __syncthreads();
        if (tid == 0) {
            float t1 = 0.f, t2 = 0.f;
#pragma unroll
            for (int i = 0; i < 8; i++) { t1 += red1[i]; t2 += red2[i]; }
            float mean = t1 * (1.0f / E);
            float var  = t2 * (1.0f / E) - mean * mean;
            stats[0] = mean;
            stats[1] = rsqrtf(fmaxf(var, 0.f) + 1e-5f);
        }
        __syncthreads();
        float mean = stats[0], rstd = stats[1];
        float4 g4 = ((const float4*)(ln1_g + (size_t)nb * E))[tid];
        float4 b4 = ((const float4*)(ln1_b + (size_t)nb * E))[tid];
        v.x = (v.x - mean) * rstd * g4.x + b4.x;
        v.y = (v.y - mean) * rstd * g4.y + b4.y;
        v.z = (v.z - mean) * rstd * g4.z + b4.z;
        v.w = (v.w - mean) * rstd * g4.w + b4.w;
    }
    ((float4*)g_h1)[tid] = v;
    ((float4*)hs)[tid] = v;
    __syncthreads();
    if (tid < 4) ms[tid] = cosf(hs[tid]) * cosf(phi_f[nb * 4 + tid]);
    __syncthreads();
    float f0 = ms[0], f1 = ms[1], f2 = ms[2], f3 = ms[3];

    // ---- r = relu(W1 @ m): 16 outputs per thread, coalesced ----
    const float4* w1 = (const float4*)W1 + (size_t)nb * FF;   // FF float4 rows
#pragma unroll
    for (int j = 0; j < 16; j++) {
        int ff = tid + 256 * j;
        float4 wv = w1[ff];
        g_r[ff] = fmaxf(wv.x*f0 + wv.y*f1 + wv.z*f2 + wv.w*f3, 0.f);
    }
}

// ================= K_M: M_blk = Wo_blk @ Wv_blk, all 6 blocks ==============
// grid = 768 CTAs x 256 threads: CTA -> (blk = c>>7, rows (c&127)*8..+8).
// Warp computes one row (8 float4 of Wo per lane, batched loads).
// Last CTA computes r for block 0.
__global__ void __launch_bounds__(256)
km_kernel(const float* __restrict__ Wo, const float* __restrict__ Wv,
          const float* __restrict__ W1,
          const float* __restrict__ phi_q, const float* __restrict__ phi_f,
          const float* __restrict__ ln1_g, const float* __restrict__ ln1_b,
          const float* __restrict__ ln2_g, const float* __restrict__ ln2_b)
{
    __shared__ __align__(16) float4 wv4[E * 2];   // E*8 floats = 32KB
    __shared__ bool lastc;
    const int tid = threadIdx.x, lane = tid & 31, w = tid >> 5;
    const int blk = blockIdx.x >> 7;
    const int grp = blockIdx.x & 127;

    const float4* wvg = (const float4*)(Wv + (size_t)blk * E * 8);
    for (int i = tid; i < E * 2; i += 256) wv4[i] = wvg[i];
    __syncthreads();

    const int row = grp * 8 + w;
    const float4* wo = (const float4*)(Wo + (size_t)blk * E * E + (size_t)row * E);

    float4 o4[8];
#pragma unroll
    for (int k = 0; k < 8; k++) o4[k] = wo[lane + 32 * k];

    float acc[8];
#pragma unroll
    for (int j = 0; j < 8; j++) acc[j] = 0.f;
#pragma unroll
    for (int k = 0; k < 8; k++) {
#pragma unroll
        for (int q = 0; q < 4; q++) {
            int kk = 4 * (lane + 32 * k) + q;
            float s = (q == 0) ? o4[k].x : (q == 1) ? o4[k].y
                    : (q == 2) ? o4[k].z : o4[k].w;
            float4 a = wv4[2 * kk], c = wv4[2 * kk + 1];
            acc[0] = fmaf(s, a.x, acc[0]);
            acc[1] = fmaf(s, a.y, acc[1]);
            acc[2] = fmaf(s, a.z, acc[2]);
            acc[3] = fmaf(s, a.w, acc[3]);
            acc[4] = fmaf(s, c.x, acc[4]);
            acc[5] = fmaf(s, c.y, acc[5]);
            acc[6] = fmaf(s, c.z, acc[6]);
            acc[7] = fmaf(s, c.w, acc[7]);
        }
    }
#pragma unroll
    for (int j = 0; j < 8; j++) {
#pragma unroll
        for (int o = 16; o; o >>= 1)
            acc[j] += __shfl_xor_sync(0xffffffffu, acc[j], o);
    }
    if (lane == 0) {
        float4* mrow = (float4*)(g_M + ((size_t)blk * E + row) * 8);
        mrow[0] = make_float4(acc[0], acc[1], acc[2], acc[3]);
        mrow[1] = make_float4(acc[4], acc[5], acc[6], acc[7]);
    }

    // last-CTA epilogue: prologue for block 0 (needs M_0 complete)
    __threadfence();
    __syncthreads();
    if (tid == 0) {
        unsigned old = atomicAdd(&g_cnt[0], 1u);
        lastc = (old == gridDim.x - 1);
    }
    __syncthreads();
    if (lastc) {
        __threadfence();                    // acquire: see peer CTAs' g_M writes
        block_prologue(0, W1, phi_q, phi_f, ln1_g, ln1_b, ln2_g, ln2_b);
        __syncthreads();
        if (tid == 0) g_cnt[0] = 0;        // replay-safe reset
    }
}

// ================= K_DOT(blk): f = W2_blk @ r  =============================
// grid = 1024 CTAs x 256 threads; CTA = one W2 row (16KB). Pure stream.
// Last CTA runs the prologue for block blk+1 (or final LN2 for blk==5).
__global__ void __launch_bounds__(256)
kdot_kernel(int blk, const float* __restrict__ W2,
            const float* __restrict__ W1,
            const float* __restrict__ phi_q, const float* __restrict__ phi_f,
            const float* __restrict__ ln1_g, const float* __restrict__ ln1_b,
            const float* __restrict__ ln2_g, const float* __restrict__ ln2_b)
{
    __shared__ float red[8];
    __shared__ bool lastc;
    const int tid = threadIdx.x, lane = tid & 31, w = tid >> 5;
    const int row = blockIdx.x;

    const float4* wr = (const float4*)W2 + (size_t)blk * E * (FF / 4)
                     + (size_t)row * (FF / 4);
    const float4* r4 = (const float4*)g_r;

    float acc = 0.f;
#pragma unroll
    for (int j = 0; j < 4; j++) {
        int idx = tid + 256 * j;
        acc += dot4(wr[idx], r4[idx]);
    }
#pragma unroll
    for (int o = 16; o; o >>= 1) acc += __shfl_xor_sync(0xffffffffu, acc, o);
    if (lane == 0) red[w] = acc;
    __syncthreads();
    if (tid == 0) {
        float s = red[0] + red[1] + red[2] + red[3]
                + red[4] + red[5] + red[6] + red[7];
        g_f[row] = s;
        __threadfence();
        unsigned old = atomicAdd(&g_cnt[1 + blk], 1u);
        lastc = (old == gridDim.x - 1);
    }
    __syncthreads();
    if (lastc) {
        __threadfence();                    // acquire: see peer CTAs' g_f writes
        block_prologue(blk + 1, W1, phi_q, phi_f, ln1_g, ln1_b, ln2_g, ln2_b);
        __syncthreads();
        if (tid == 0) g_cnt[1 + blk] = 0;  // replay-safe reset
    }
}

// ================= K_CLS: classifier row via g_hfin ========================
// grid = 1000 CTAs x 256 threads; CTA = one Wc row (4KB).
__global__ void __launch_bounds__(256)
kcls_kernel(const float* __restrict__ Wc, const float* __restrict__ bc)
{
    __shared__ float red[8];
    const int tid = threadIdx.x, lane = tid & 31, w = tid >> 5;
    const int row = blockIdx.x;

    const float4* wr = (const float4*)Wc + (size_t)row * (E / 4);
    const float4* h4 = (const float4*)g_hfin;
    float acc = dot4(wr[tid], h4[tid]);
#pragma unroll
    for (int o = 16; o; o >>= 1) acc += __shfl_xor_sync(0xffffffffu, acc, o);
    if (lane == 0) red[w] = acc;
    __syncthreads();
    if (tid == 0) {
        float s = red[0] + red[1] + red[2] + red[3]
                + red[4] + red[5] + red[6] + red[7];
        g_row[row] = s + bc[row];
    }
}

// ================= K_BCAST: broadcast row to all B output rows =============
__global__ void __launch_bounds__(1024)
kb_kernel(float* __restrict__ out)
{
    __shared__ __align__(16) float row_s[CC];
    const int tid = threadIdx.x, lane = tid & 31;
    if (tid < CC) row_s[tid] = g_row[tid];
    __syncthreads();

    const int gwarp = blockIdx.x * 32 + (tid >> 5);
    const int nwarps = gridDim.x * 32;
    const float4* r4 = (const float4*)row_s;               // 250 float4
    for (int r = gwarp; r < BB; r += nwarps) {
        float4* dst = (float4*)out + (size_t)r * (CC / 4);
        for (int j = lane; j < CC / 4; j += 32) dst[j] = r4[j];
    }
}

// ================= host launch =============================================
extern "C" void kernel_launch(void* const* d_in, const int* in_sizes, int n_in,
                              void* d_out, int out_size) {
    // metadata order: 0:x 1:Wq 2:Wk 3:Wv 4:Wo 5:phi_q 6:W1 7:W2 8:phi_f
    //                 9:ln1_g 10:ln1_b 11:ln2_g 12:ln2_b 13:Wc 14:bc
    const float* Wv    = (const float*)d_in[3];
    const float* Wo    = (const float*)d_in[4];
    const float* phi_q = (const float*)d_in[5];
    const float* W1    = (const float*)d_in[6];
    const float* W2    = (const float*)d_in[7];
    const float* phi_f = (const float*)d_in[8];
    const float* ln1_g = (const float*)d_in[9];
    const float* ln1_b = (const float*)d_in[10];
    const float* ln2_g = (const float*)d_in[11];
    const float* ln2_b = (const float*)d_in[12];
    const float* Wc    = (const float*)d_in[13];
    const float* bc    = (const float*)d_in[14];

    km_kernel<<<768, 256>>>(Wo, Wv, W1, phi_q, phi_f,
                            ln1_g, ln1_b, ln2_g, ln2_b);
    for (int blk = 0; blk < NBLK; blk++)
        kdot_kernel<<<1024, 256>>>(blk, W2, W1, phi_q, phi_f,
                                   ln1_g, ln1_b, ln2_g, ln2_b);
    kcls_kernel<<<1000, 256>>>(Wc, bc);
    kb_kernel<<<148, 1024>>>((float*)d_out);
}

// round 12
// speedup vs baseline: 1.7263x; 1.7263x over previous
#include <cuda_runtime.h>
#include <cstdint>

// Problem constants (fixed by the reference)
#define E    1024
#define NBLK 6
#define FF   4096
#define CC   1000
#define BB   4096

// ---------------- device scratch (no allocations allowed) ----------------
__device__ __align__(16) float g_M[NBLK * E * 8]; // precomputed Wo@Wv (E x 8 per block)
__device__ __align__(16) float g_f[2][E];         // f vector, double-buffered by parity
__device__ __align__(16) float g_h1[2][E];        // h-after-LN1, double-buffered
__device__ __align__(16) float g_row[CC];         // classifier row

__device__ __forceinline__ float dot4(float4 a, float4 b) {
    return fmaf(a.x, b.x, fmaf(a.y, b.y, fmaf(a.z, b.z, a.w * b.w)));
}

// LayerNorm stats over E values (one per thread, 1024 threads).
__device__ __forceinline__ void ln_stats(float val, float* red1, float* red2,
                                         float* stats, int lane, int wc) {
    float s1 = val, s2 = val * val;
#pragma unroll
    for (int o = 16; o; o >>= 1) {
        s1 += __shfl_xor_sync(0xffffffffu, s1, o);
        s2 += __shfl_xor_sync(0xffffffffu, s2, o);
    }
    if (lane == 0) { red1[wc] = s1; red2[wc] = s2; }
    __syncthreads();
    if (wc == 0) {
        float a = red1[lane], c = red2[lane];
#pragma unroll
        for (int o = 16; o; o >>= 1) {
            a += __shfl_xor_sync(0xffffffffu, a, o);
            c += __shfl_xor_sync(0xffffffffu, c, o);
        }
        if (lane == 0) {
            float mean = a * (1.0f / E);
            float var  = c * (1.0f / E) - mean * mean;
            stats[0] = mean;
            stats[1] = rsqrtf(fmaxf(var, 0.f) + 1e-5f);
        }
    }
    __syncthreads();
}

// ================= K_M: M_blk = Wo_blk @ Wv_blk  (E x 8 per block) =========
// grid = 192 CTAs x 256 threads: CTA c -> blk = c/32, rows (c%32)*32 .. +32.
// Wo is read with __ldcs (evict-first): used once per launch, and we want L2
// to keep W2/Wc resident across graph replays instead.
__global__ void __launch_bounds__(256)
km_kernel(const float* __restrict__ Wo, const float* __restrict__ Wv)
{
    __shared__ __align__(16) float wv_s[E * 8];   // 32KB
    const int tid = threadIdx.x, lane = tid & 31, w = tid >> 5;
    const int blk  = blockIdx.x >> 5;
    const int row0 = (blockIdx.x & 31) * 32;

    const float4* wvg = (const float4*)(Wv + (size_t)blk * E * 8);
    float4* wv4 = (float4*)wv_s;
    for (int i = tid; i < E * 8 / 4; i += 256) wv4[i] = wvg[i];
    __syncthreads();

    const int r0 = row0 + 4 * w;
    const float* wo0 = Wo + (size_t)blk * E * E + (size_t)r0 * E;

    float acc[4][8];
#pragma unroll
    for (int r = 0; r < 4; r++)
#pragma unroll
        for (int j = 0; j < 8; j++) acc[r][j] = 0.f;

#pragma unroll
    for (int kk = 0; kk < 8; kk++) {
        int k4 = lane + 32 * kk;
        float4 wo4[4];
#pragma unroll
        for (int r = 0; r < 4; r++)
            wo4[r] = __ldcs((const float4*)(wo0 + (size_t)r * E) + k4);
#pragma unroll
        for (int q = 0; q < 4; q++) {
            int k = 4 * k4 + q;
            float4 a = wv4[2 * k], c = wv4[2 * k + 1];
#pragma unroll
            for (int r = 0; r < 4; r++) {
                float s = (q == 0) ? wo4[r].x : (q == 1) ? wo4[r].y
                        : (q == 2) ? wo4[r].z : wo4[r].w;
                acc[r][0] = fmaf(s, a.x, acc[r][0]);
                acc[r][1] = fmaf(s, a.y, acc[r][1]);
                acc[r][2] = fmaf(s, a.z, acc[r][2]);
                acc[r][3] = fmaf(s, a.w, acc[r][3]);
                acc[r][4] = fmaf(s, c.x, acc[r][4]);
                acc[r][5] = fmaf(s, c.y, acc[r][5]);
                acc[r][6] = fmaf(s, c.z, acc[r][6]);
                acc[r][7] = fmaf(s, c.w, acc[r][7]);
            }
        }
    }
#pragma unroll
    for (int r = 0; r < 4; r++) {
#pragma unroll
        for (int j = 0; j < 8; j++) {
#pragma unroll
            for (int o = 16; o; o >>= 1)
                acc[r][j] += __shfl_xor_sync(0xffffffffu, acc[r][j], o);
        }
        if (lane == 0) {
            float4* mrow = (float4*)(g_M + ((size_t)blk * E + r0 + r) * 8);
            mrow[0] = make_float4(acc[r][0], acc[r][1], acc[r][2], acc[r][3]);
            mrow[1] = make_float4(acc[r][4], acc[r][5], acc[r][6], acc[r][7]);
        }
    }
}

// ================= K_F(blk): one transformer block ==========================
// grid = 148 CTAs x 1024. CTA b owns W2 rows [7b, 7b+7).
// W2 slice loaded into registers at entry (default caching -> L2-resident
// across replays); prologue overlaps the loads; then FMA against r_s.
__global__ void __launch_bounds__(1024)
kf_kernel(int blk,
          const float* __restrict__ W1,   const float* __restrict__ W2,
          const float* __restrict__ phi_q, const float* __restrict__ phi_f,
          const float* __restrict__ ln1_g, const float* __restrict__ ln1_b,
          const float* __restrict__ ln2_g, const float* __restrict__ ln2_b)
{
    __shared__ __align__(16) float r_s[FF];
    __shared__ __align__(16) float h_s[E];
    __shared__ float red1[32], red2[32], stats[2], m_s[8];
    __shared__ float red_dot[7][4];

    const int tid = threadIdx.x, lane = tid & 31, wc = tid >> 5;
    const int b = blockIdx.x;
    const int cur = blk & 1, prev = (blk + 1) & 1;

    const int i = wc >> 2;                 // 0..7 row within CTA (7 valid)
    const int p = wc & 3;                  // 0..3 row segment
    const int row = b * 7 + i;
    const bool active = (i < 7) && (row < E);

    // ---- 1) issue W2 row-slice loads into registers (fire-and-forget) ----
    float4 wreg[8];
    if (active) {
        const float4* src = (const float4*)W2 + (size_t)blk * E * (FF / 4)
                          + (size_t)row * (FF / 4) + p * 256 + lane;
#pragma unroll
        for (int j = 0; j < 8; j++) wreg[j] = src[32 * j];
    }

    // ---- 2) prologue (overlaps the in-flight loads) ----
    float hp;
    if (blk == 0) {
        hp = 1.0f + (float)(tid & 1);                    // h0 = [1,2,1,2,...]
    } else {
        float val = g_h1[prev][tid] + g_f[prev][tid];
        ln_stats(val, red1, red2, stats, lane, wc);
        hp = (val - stats[0]) * stats[1] * ln2_g[(blk - 1) * E + tid]
           + ln2_b[(blk - 1) * E + tid];
    }
    h_s[tid] = hp;
    __syncthreads();
    if (tid < 8) m_s[tid] = cosf(h_s[tid] + phi_q[blk * 8 + tid]);
    __syncthreads();
    float attn;
    {
        const float4* mrow = (const float4*)(g_M + ((size_t)blk * E + tid) * 8);
        float4 a = mrow[0], c = mrow[1];
        attn = a.x * m_s[0] + a.y * m_s[1] + a.z * m_s[2] + a.w * m_s[3]
             + c.x * m_s[4] + c.y * m_s[5] + c.z * m_s[6] + c.w * m_s[7];
    }
    float h1;
    {
        float val = hp + attn;
        ln_stats(val, red1, red2, stats, lane, wc);
        h1 = (val - stats[0]) * stats[1] * ln1_g[blk * E + tid]
           + ln1_b[blk * E + tid];
    }
    if (b == 0) g_h1[cur][tid] = h1;                      // for next node
    h_s[tid] = h1;
    __syncthreads();
    if (tid < 4) m_s[tid] = cosf(h_s[tid]) * cosf(phi_f[blk * 4 + tid]);
    __syncthreads();
    {
        const float4* w1 = (const float4*)W1 + (size_t)blk * FF;  // FF float4 rows
        float m0 = m_s[0], m1 = m_s[1], m2 = m_s[2], m3 = m_s[3];
#pragma unroll
        for (int j = 0; j < FF / 1024; j++) {
            int ff = tid + j * 1024;
            float4 w = w1[ff];
            r_s[ff] = fmaxf(w.x * m0 + w.y * m1 + w.z * m2 + w.w * m3, 0.f);
        }
    }
    __syncthreads();

    // ---- 3) dot register-resident W2 slice against r ----
    if (active) {
        const float4* r4 = (const float4*)r_s;
        float acc = 0.f;
#pragma unroll
        for (int j = 0; j < 8; j++)
            acc += dot4(wreg[j], r4[p * 256 + lane + 32 * j]);
#pragma unroll
        for (int o = 16; o; o >>= 1) acc += __shfl_xor_sync(0xffffffffu, acc, o);
        if (lane == 0) red_dot[i][p] = acc;
    }
    __syncthreads();
    if (tid < 7 && b * 7 + tid < E) {
        float s = red_dot[tid][0] + red_dot[tid][1] + red_dot[tid][2] + red_dot[tid][3];
        g_f[cur][b * 7 + tid] = s;
    }
}

// ================= K_CLS: LN2-final + classifier ===========================
// grid = 125 CTAs x 1024. CTA b owns Wc rows [8b, 8b+8); default caching.
__global__ void __launch_bounds__(1024)
kcls_kernel(const float* __restrict__ Wc, const float* __restrict__ bc,
            const float* __restrict__ ln2_g, const float* __restrict__ ln2_b)
{
    __shared__ __align__(16) float h_s[E];
    __shared__ float red1[32], red2[32], stats[2];
    __shared__ float red_cls[8][4];

    const int tid = threadIdx.x, lane = tid & 31, wc = tid >> 5;
    const int b = blockIdx.x;
    const int r = wc >> 2, p = wc & 3;         // 8 rows x 4 warp-parts

    // issue Wc loads into registers first (overlap with LN)
    float4 w0, w1;
    {
        const float4* src = (const float4*)Wc + ((size_t)b * 8 + r) * 256;
        w0 = src[p * 64 + lane];
        w1 = src[p * 64 + lane + 32];
    }

    // h_final = LN2 of block 5 (parity: 5&1 = 1)
    {
        float val = g_h1[1][tid] + g_f[1][tid];
        ln_stats(val, red1, red2, stats, lane, wc);
        h_s[tid] = (val - stats[0]) * stats[1] * ln2_g[5 * E + tid]
                 + ln2_b[5 * E + tid];
    }
    __syncthreads();

    const float4* h4 = (const float4*)h_s;
    float acc = dot4(w0, h4[p * 64 + lane]) + dot4(w1, h4[p * 64 + lane + 32]);
#pragma unroll
    for (int o = 16; o; o >>= 1) acc += __shfl_xor_sync(0xffffffffu, acc, o);
    if (lane == 0) red_cls[r][p] = acc;
    __syncthreads();
    if (tid < 8) {
        float s = red_cls[tid][0] + red_cls[tid][1] + red_cls[tid][2] + red_cls[tid][3];
        g_row[b * 8 + tid] = s + bc[b * 8 + tid];
    }
}

// ================= K_BCAST: broadcast row to all B output rows =============
// __stwt: write-through, no L2 allocation -> the 16.4MB output stream does
// not evict the L2-resident weights between graph replays.
__global__ void __launch_bounds__(1024)
kb_kernel(float* __restrict__ out)
{
    __shared__ __align__(16) float row_s[CC];
    const int tid = threadIdx.x, lane = tid & 31;
    if (tid < CC) row_s[tid] = g_row[tid];
    __syncthreads();

    const int gwarp = blockIdx.x * 32 + (tid >> 5);
    const int nwarps = gridDim.x * 32;
    const float4* r4 = (const float4*)row_s;               // 250 float4
    for (int r = gwarp; r < BB; r += nwarps) {
        float4* dst = (float4*)out + (size_t)r * (CC / 4);
        for (int j = lane; j < CC / 4; j += 32)
            __stwt(dst + j, r4[j]);
    }
}

// ================= host launch =============================================
extern "C" void kernel_launch(void* const* d_in, const int* in_sizes, int n_in,
                              void* d_out, int out_size) {
    // metadata order: 0:x 1:Wq 2:Wk 3:Wv 4:Wo 5:phi_q 6:W1 7:W2 8:phi_f
    //                 9:ln1_g 10:ln1_b 11:ln2_g 12:ln2_b 13:Wc 14:bc
    const float* Wv    = (const float*)d_in[3];
    const float* Wo    = (const float*)d_in[4];
    const float* phi_q = (const float*)d_in[5];
    const float* W1    = (const float*)d_in[6];
    const float* W2    = (const float*)d_in[7];
    const float* phi_f = (const float*)d_in[8];
    const float* ln1_g = (const float*)d_in[9];
    const float* ln1_b = (const float*)d_in[10];
    const float* ln2_g = (const float*)d_in[11];
    const float* ln2_b = (const float*)d_in[12];
    const float* Wc    = (const float*)d_in[13];
    const float* bc    = (const float*)d_in[14];

    km_kernel<<<192, 256>>>(Wo, Wv);
    for (int blk = 0; blk < NBLK; blk++)
        kf_kernel<<<148, 1024>>>(blk, W1, W2, phi_q, phi_f,
                                 ln1_g, ln1_b, ln2_g, ln2_b);
    kcls_kernel<<<125, 1024>>>(Wc, bc, ln2_g, ln2_b);
    kb_kernel<<<148, 1024>>>((float*)d_out);
}